// round 3
// baseline (speedup 1.0000x reference)
#include <cuda_runtime.h>

#define N_NODES 10000
#define D_IN    128
#define H1      128
#define H2      64
#define EMB     64
#define MAX_E   650000
#define NEG_SLOPE 0.2f

// ---------------- scratch (device globals; no allocation allowed) -----------
__device__ float g_h1[N_NODES * H1];
__device__ float g_x1[N_NODES * H1];
__device__ float g_h2[N_NODES * H2];
__device__ float g_x2[N_NODES * H2];
__device__ float g_as[N_NODES];
__device__ float g_ad[N_NODES];
__device__ int   g_deg[N_NODES];
__device__ int   g_rowptr[N_NODES + 1];
__device__ int   g_cursor[N_NODES];
__device__ int   g_csr[MAX_E];

// device-side scratch selector (host never touches device symbols)
__device__ __forceinline__ float* buf(int sel) {
    switch (sel) {
        case 0: return g_h1;
        case 1: return g_x1;
        case 2: return g_h2;
        default: return g_x2;
    }
}

// ---------------- CSR construction ------------------------------------------
__global__ void zero_deg_kernel() {
    int i = blockIdx.x * blockDim.x + threadIdx.x;
    if (i < N_NODES) g_deg[i] = 0;
}

// edge_index is int32: row 0 = src (E entries), row 1 = dst (E entries)
__global__ void hist_kernel(const int* __restrict__ ei, int E) {
    int e = blockIdx.x * blockDim.x + threadIdx.x;
    if (e < E) {
        int d = ei[E + e];
        if ((unsigned)d < N_NODES) atomicAdd(&g_deg[d], 1);
    }
}

// single-block exclusive scan of g_deg -> g_rowptr (+ cursor copy)
__global__ void scan_kernel() {
    __shared__ int sh[1024];
    const int tid = threadIdx.x;
    const int PER = 10;                    // 1024*10 = 10240 >= 10001
    int vals[PER];
    int base = tid * PER;
    int s = 0;
#pragma unroll
    for (int k = 0; k < PER; k++) {
        int idx = base + k;
        int v = (idx < N_NODES) ? g_deg[idx] : 0;
        vals[k] = v;
        s += v;
    }
    sh[tid] = s;
    __syncthreads();
    for (int off = 1; off < 1024; off <<= 1) {
        int v = (tid >= off) ? sh[tid - off] : 0;
        __syncthreads();
        sh[tid] += v;
        __syncthreads();
    }
    int run = sh[tid] - s;                 // exclusive prefix
#pragma unroll
    for (int k = 0; k < PER; k++) {
        int idx = base + k;
        if (idx <= N_NODES) {
            g_rowptr[idx] = run;
            if (idx < N_NODES) g_cursor[idx] = run;
        }
        run += vals[k];
    }
}

__global__ void fill_kernel(const int* __restrict__ ei, int E) {
    int e = blockIdx.x * blockDim.x + threadIdx.x;
    if (e < E) {
        int s = ei[e];
        int d = ei[E + e];
        if ((unsigned)s < N_NODES && (unsigned)d < N_NODES) {
            int pos = atomicAdd(&g_cursor[d], 1);
            if (pos < MAX_E) g_csr[pos] = s;
        }
    }
}

// ---------------- fp32 tiled GEMM: C[M,Nn] = A[M,K] @ B[K,Nn] (+bias) -------
__global__ void gemm_kernel(const float* __restrict__ Aext, int a_sel,
                            const float* __restrict__ B,
                            const float* __restrict__ bias,
                            float* __restrict__ Cext, int c_sel,
                            int M, int Nn, int K) {
    const float* A = Aext ? Aext : buf(a_sel);
    float*       C = Cext ? Cext : buf(c_sel);

    __shared__ __align__(16) float As[8][64];
    __shared__ __align__(16) float Bs[8][64];
    const int tid  = threadIdx.x;             // 256 threads
    const int trow = tid >> 4;                // 0..15
    const int tcol = tid & 15;                // 0..15
    const int m0 = blockIdx.y * 64;
    const int n0 = blockIdx.x * 64;
    float acc[4][4] = {};

    for (int k0 = 0; k0 < K; k0 += 8) {
        for (int t = tid; t < 512; t += 256) {
            int r = t >> 3, c = t & 7;
            int gr = m0 + r;
            As[c][r] = (gr < M) ? A[gr * K + k0 + c] : 0.f;
        }
        for (int t = tid; t < 512; t += 256) {
            int r = t >> 6, c = t & 63;
            Bs[r][c] = B[(k0 + r) * Nn + n0 + c];
        }
        __syncthreads();
#pragma unroll
        for (int kk = 0; kk < 8; kk++) {
            float4 a4 = *(const float4*)&As[kk][trow * 4];
            float4 b4 = *(const float4*)&Bs[kk][tcol * 4];
            float a[4] = {a4.x, a4.y, a4.z, a4.w};
            float b[4] = {b4.x, b4.y, b4.z, b4.w};
#pragma unroll
            for (int i = 0; i < 4; i++)
#pragma unroll
                for (int j = 0; j < 4; j++)
                    acc[i][j] += a[i] * b[j];
        }
        __syncthreads();
    }

#pragma unroll
    for (int i = 0; i < 4; i++) {
        int row = m0 + trow * 4 + i;
        if (row < M) {
#pragma unroll
            for (int j = 0; j < 4; j++) {
                int col = n0 + tcol * 4 + j;
                float v = acc[i][j];
                if (bias) v += bias[col];
                C[row * Nn + col] = v;
            }
        }
    }
}

// ---------------- per-node attention dot products ---------------------------
__global__ void attn_dots_kernel(int h_sel,
                                 const float* __restrict__ a_src,
                                 const float* __restrict__ a_dst, int H) {
    const float* h = buf(h_sel);
    int warp = (blockIdx.x * blockDim.x + threadIdx.x) >> 5;
    if (warp >= N_NODES) return;
    int lane = threadIdx.x & 31;
    float s1 = 0.f, s2 = 0.f;
    for (int d = lane; d < H; d += 32) {
        float v = h[warp * H + d];
        s1 += v * a_src[d];
        s2 += v * a_dst[d];
    }
#pragma unroll
    for (int o = 16; o; o >>= 1) {
        s1 += __shfl_xor_sync(0xffffffffu, s1, o);
        s2 += __shfl_xor_sync(0xffffffffu, s2, o);
    }
    if (!lane) {
        g_as[warp] = s1;
        g_ad[warp] = s2;
    }
}

__device__ __forceinline__ float leaky(float x) {
    return x > 0.f ? x : NEG_SLOPE * x;
}

// ---------------- GAT aggregation: warp per destination node ----------------
template <int H>
__global__ void gat_agg_kernel(const float* __restrict__ bias) {
    const float* h;
    float* out;
    if (H == 128) { h = g_h1; out = g_x1; }
    else          { h = g_h2; out = g_x2; }

    int i = (blockIdx.x * blockDim.x + threadIdx.x) >> 5;
    if (i >= N_NODES) return;
    int lane = threadIdx.x & 31;

    float adi = g_ad[i];
    int beg = g_rowptr[i], end = g_rowptr[i + 1];

    // denominator z (lane-parallel over edges)
    float z = 0.f;
    for (int j = beg + lane; j < end; j += 32)
        z += __expf(leaky(g_as[g_csr[j]] + adi));
#pragma unroll
    for (int o = 16; o; o >>= 1) z += __shfl_xor_sync(0xffffffffu, z, o);

    // self loop
    float es = __expf(leaky(g_as[i] + adi));
    z += es;
    float inv = 1.f / z;

    constexpr int V = H / 32;
    float acc[V];
#pragma unroll
    for (int v = 0; v < V; v++) acc[v] = es * h[i * H + lane * V + v];

    for (int j = beg; j < end; ++j) {
        int s = g_csr[j];                         // lane-uniform
        float e = __expf(leaky(g_as[s] + adi));
        if (V == 4) {
            float4 hv = *(const float4*)&h[s * H + lane * 4];
            acc[0] += e * hv.x; acc[1] += e * hv.y;
            acc[2] += e * hv.z; acc[3] += e * hv.w;
        } else {
            float2 hv = *(const float2*)&h[s * H + lane * 2];
            acc[0] += e * hv.x; acc[1] += e * hv.y;
        }
    }

#pragma unroll
    for (int v = 0; v < V; v++) {
        float r = acc[v] * inv + bias[lane * V + v];
        out[i * H + lane * V + v] = r > 0.f ? r : 0.f;
    }
}

// ---------------- launch -----------------------------------------------------
extern "C" void kernel_launch(void* const* d_in, const int* in_sizes, int n_in,
                              void* d_out, int out_size) {
    const float* x    = (const float*)d_in[0];
    const int*   ei   = (const int*)d_in[1];       // int32 edge_index [2, E]
    const float* W1   = (const float*)d_in[2];
    const float* a_s1 = (const float*)d_in[3];
    const float* a_d1 = (const float*)d_in[4];
    const float* b1   = (const float*)d_in[5];
    const float* W2   = (const float*)d_in[6];
    const float* a_s2 = (const float*)d_in[7];
    const float* a_d2 = (const float*)d_in[8];
    const float* b2   = (const float*)d_in[9];
    const float* Wp   = (const float*)d_in[10];
    const float* bp   = (const float*)d_in[11];
    const int E = in_sizes[1] / 2;

    const int TB = 256;
    // CSR build
    zero_deg_kernel<<<(N_NODES + TB - 1) / TB, TB>>>();
    hist_kernel<<<(E + TB - 1) / TB, TB>>>(ei, E);
    scan_kernel<<<1, 1024>>>();
    fill_kernel<<<(E + TB - 1) / TB, TB>>>(ei, E);

    const int warpBlocks = (N_NODES * 32 + TB - 1) / TB;

    // layer 1: h1 = x @ W1 ; attention ; x1 = agg(h1)
    dim3 g1(H1 / 64, (N_NODES + 63) / 64);
    gemm_kernel<<<g1, TB>>>(x, -1, W1, nullptr, nullptr, 0, N_NODES, H1, D_IN);
    attn_dots_kernel<<<warpBlocks, TB>>>(0, a_s1, a_d1, H1);
    gat_agg_kernel<H1><<<warpBlocks, TB>>>(b1);

    // layer 2: h2 = x1 @ W2 ; attention ; x2 = agg(h2)
    dim3 g2(H2 / 64, (N_NODES + 63) / 64);
    gemm_kernel<<<g2, TB>>>(nullptr, 1, W2, nullptr, nullptr, 2, N_NODES, H2, H1);
    attn_dots_kernel<<<warpBlocks, TB>>>(2, a_s2, a_d2, H2);
    gat_agg_kernel<H2><<<warpBlocks, TB>>>(b2);

    // projection: out = x2 @ Wp + bp
    dim3 g3(EMB / 64, (N_NODES + 63) / 64);
    gemm_kernel<<<g3, TB>>>(nullptr, 3, Wp, bp, (float*)d_out, -1, N_NODES, EMB, H2);
}

// round 4
// speedup vs baseline: 1.0396x; 1.0396x over previous
#include <cuda_runtime.h>

#define N_NODES 10000
#define D_IN    128
#define H1      128
#define H2      64
#define EMB     64
#define MAX_E   650000
#define NEG_SLOPE 0.2f

// ---------------- scratch (device globals; no allocation allowed) -----------
__device__ float g_h1[N_NODES * H1];
__device__ float g_x1[N_NODES * H1];
__device__ float g_h2[N_NODES * H2];
__device__ float g_x2[N_NODES * H2];
__device__ float g_as[N_NODES];
__device__ float g_ad[N_NODES];
__device__ int   g_deg[N_NODES];
__device__ int   g_rowptr[N_NODES + 1];
__device__ int   g_cursor[N_NODES];
__device__ int   g_csr[MAX_E];

// device-side scratch selector (host never touches device symbols)
__device__ __forceinline__ float* buf(int sel) {
    switch (sel) {
        case 0: return g_h1;
        case 1: return g_x1;
        case 2: return g_h2;
        default: return g_x2;
    }
}

// ---------------- CSR construction ------------------------------------------
__global__ void zero_deg_kernel() {
    int i = blockIdx.x * blockDim.x + threadIdx.x;
    if (i < N_NODES) {
        g_deg[i] = 0;
        g_as[i] = 0.f;
        g_ad[i] = 0.f;
    }
}

__global__ void zero_attn_kernel() {
    int i = blockIdx.x * blockDim.x + threadIdx.x;
    if (i < N_NODES) {
        g_as[i] = 0.f;
        g_ad[i] = 0.f;
    }
}

// edge_index is int32: row 0 = src (E entries), row 1 = dst (E entries)
// 4 edges per thread for atomic-latency hiding
__global__ void hist_kernel(const int* __restrict__ ei, int E) {
    int t = blockIdx.x * blockDim.x + threadIdx.x;
    int e0 = t * 4;
    if (e0 + 4 <= E && ((E & 3) == 0)) {
        int4 d4 = *(const int4*)&ei[E + e0];
        if ((unsigned)d4.x < N_NODES) atomicAdd(&g_deg[d4.x], 1);
        if ((unsigned)d4.y < N_NODES) atomicAdd(&g_deg[d4.y], 1);
        if ((unsigned)d4.z < N_NODES) atomicAdd(&g_deg[d4.z], 1);
        if ((unsigned)d4.w < N_NODES) atomicAdd(&g_deg[d4.w], 1);
    } else {
        for (int e = e0; e < E && e < e0 + 4; e++) {
            int d = ei[E + e];
            if ((unsigned)d < N_NODES) atomicAdd(&g_deg[d], 1);
        }
    }
}

// single-block exclusive scan of g_deg -> g_rowptr (+ cursor copy)
__global__ void scan_kernel() {
    __shared__ int sh[1024];
    const int tid = threadIdx.x;
    const int PER = 10;                    // 1024*10 = 10240 >= 10001
    int vals[PER];
    int base = tid * PER;
    int s = 0;
#pragma unroll
    for (int k = 0; k < PER; k++) {
        int idx = base + k;
        int v = (idx < N_NODES) ? g_deg[idx] : 0;
        vals[k] = v;
        s += v;
    }
    sh[tid] = s;
    __syncthreads();
    for (int off = 1; off < 1024; off <<= 1) {
        int v = (tid >= off) ? sh[tid - off] : 0;
        __syncthreads();
        sh[tid] += v;
        __syncthreads();
    }
    int run = sh[tid] - s;                 // exclusive prefix
#pragma unroll
    for (int k = 0; k < PER; k++) {
        int idx = base + k;
        if (idx <= N_NODES) {
            g_rowptr[idx] = run;
            if (idx < N_NODES) g_cursor[idx] = run;
        }
        run += vals[k];
    }
}

__global__ void fill_kernel(const int* __restrict__ ei, int E) {
    int t = blockIdx.x * blockDim.x + threadIdx.x;
    int e0 = t * 4;
    if (e0 + 4 <= E && ((E & 3) == 0)) {
        int4 s4 = *(const int4*)&ei[e0];
        int4 d4 = *(const int4*)&ei[E + e0];
        int p0 = ((unsigned)d4.x < N_NODES) ? atomicAdd(&g_cursor[d4.x], 1) : MAX_E;
        int p1 = ((unsigned)d4.y < N_NODES) ? atomicAdd(&g_cursor[d4.y], 1) : MAX_E;
        int p2 = ((unsigned)d4.z < N_NODES) ? atomicAdd(&g_cursor[d4.z], 1) : MAX_E;
        int p3 = ((unsigned)d4.w < N_NODES) ? atomicAdd(&g_cursor[d4.w], 1) : MAX_E;
        if (p0 < MAX_E) g_csr[p0] = s4.x;
        if (p1 < MAX_E) g_csr[p1] = s4.y;
        if (p2 < MAX_E) g_csr[p2] = s4.z;
        if (p3 < MAX_E) g_csr[p3] = s4.w;
    } else {
        for (int e = e0; e < E && e < e0 + 4; e++) {
            int s = ei[e];
            int d = ei[E + e];
            if ((unsigned)s < N_NODES && (unsigned)d < N_NODES) {
                int pos = atomicAdd(&g_cursor[d], 1);
                if (pos < MAX_E) g_csr[pos] = s;
            }
        }
    }
}

// ---------------- fp32 tiled GEMM: C[M,Nn] = A[M,K] @ B[K,Nn] (+bias) -------
// If a_src != nullptr, also accumulates per-row attention dots into g_as/g_ad
// (which must be zeroed beforehand).
__global__ void gemm_kernel(const float* __restrict__ Aext, int a_sel,
                            const float* __restrict__ B,
                            const float* __restrict__ bias,
                            float* __restrict__ Cext, int c_sel,
                            int M, int Nn, int K,
                            const float* __restrict__ a_src,
                            const float* __restrict__ a_dst) {
    const float* A = Aext ? Aext : buf(a_sel);
    float*       C = Cext ? Cext : buf(c_sel);

    __shared__ __align__(16) float As[8][64];
    __shared__ __align__(16) float Bs[8][64];
    const int tid  = threadIdx.x;             // 256 threads
    const int trow = tid >> 4;                // 0..15
    const int tcol = tid & 15;                // 0..15
    const int m0 = blockIdx.y * 64;
    const int n0 = blockIdx.x * 64;
    float acc[4][4] = {};

    for (int k0 = 0; k0 < K; k0 += 8) {
        for (int t = tid; t < 512; t += 256) {
            int r = t >> 3, c = t & 7;
            int gr = m0 + r;
            As[c][r] = (gr < M) ? A[gr * K + k0 + c] : 0.f;
        }
        for (int t = tid; t < 512; t += 256) {
            int r = t >> 6, c = t & 63;
            Bs[r][c] = B[(k0 + r) * Nn + n0 + c];
        }
        __syncthreads();
#pragma unroll
        for (int kk = 0; kk < 8; kk++) {
            float4 a4 = *(const float4*)&As[kk][trow * 4];
            float4 b4 = *(const float4*)&Bs[kk][tcol * 4];
            float a[4] = {a4.x, a4.y, a4.z, a4.w};
            float b[4] = {b4.x, b4.y, b4.z, b4.w};
#pragma unroll
            for (int i = 0; i < 4; i++)
#pragma unroll
                for (int j = 0; j < 4; j++)
                    acc[i][j] += a[i] * b[j];
        }
        __syncthreads();
    }

#pragma unroll
    for (int i = 0; i < 4; i++) {
        int row = m0 + trow * 4 + i;
        if (row < M) {
#pragma unroll
            for (int j = 0; j < 4; j++) {
                int col = n0 + tcol * 4 + j;
                float v = acc[i][j];
                if (bias) v += bias[col];
                C[row * Nn + col] = v;
            }
        }
    }

    // fused attention dots: per-row reduction over this block's 64 columns
    if (a_src) {
        float asv[4], adv[4];
#pragma unroll
        for (int j = 0; j < 4; j++) {
            asv[j] = a_src[n0 + tcol * 4 + j];
            adv[j] = a_dst[n0 + tcol * 4 + j];
        }
#pragma unroll
        for (int i = 0; i < 4; i++) {
            float ds = 0.f, dd = 0.f;
#pragma unroll
            for (int j = 0; j < 4; j++) {
                ds += acc[i][j] * asv[j];
                dd += acc[i][j] * adv[j];
            }
            // reduce across the 16-thread column group (stays within lane group)
#pragma unroll
            for (int off = 8; off; off >>= 1) {
                ds += __shfl_xor_sync(0xffffffffu, ds, off);
                dd += __shfl_xor_sync(0xffffffffu, dd, off);
            }
            int row = m0 + trow * 4 + i;
            if (tcol == 0 && row < M) {
                atomicAdd(&g_as[row], ds);
                atomicAdd(&g_ad[row], dd);
            }
        }
    }
}

__device__ __forceinline__ float leaky(float x) {
    return x > 0.f ? x : NEG_SLOPE * x;
}

// ---------------- GAT aggregation: warp per destination node ----------------
// Single pass: accumulate unnormalized sum and z together, normalize at end.
template <int H>
__global__ void gat_agg_kernel(const float* __restrict__ bias) {
    const float* h;
    float* out;
    if (H == 128) { h = g_h1; out = g_x1; }
    else          { h = g_h2; out = g_x2; }

    int i = (blockIdx.x * blockDim.x + threadIdx.x) >> 5;
    if (i >= N_NODES) return;
    int lane = threadIdx.x & 31;

    float adi = g_ad[i];
    int beg = g_rowptr[i], end = g_rowptr[i + 1];

    constexpr int V = H / 32;
    // self loop
    float es = __expf(leaky(g_as[i] + adi));
    float z = es;
    float acc[V];
#pragma unroll
    for (int v = 0; v < V; v++) acc[v] = es * h[i * H + lane * V + v];

    int j = beg;
    // unrolled x2: two independent gathers in flight
    for (; j + 2 <= end; j += 2) {
        int s0 = __ldg(&g_csr[j]);
        int s1 = __ldg(&g_csr[j + 1]);
        float e0 = __expf(leaky(__ldg(&g_as[s0]) + adi));
        float e1 = __expf(leaky(__ldg(&g_as[s1]) + adi));
        if (V == 4) {
            float4 v0 = *(const float4*)&h[s0 * H + lane * 4];
            float4 v1 = *(const float4*)&h[s1 * H + lane * 4];
            acc[0] += e0 * v0.x + e1 * v1.x;
            acc[1] += e0 * v0.y + e1 * v1.y;
            acc[2] += e0 * v0.z + e1 * v1.z;
            acc[3] += e0 * v0.w + e1 * v1.w;
        } else {
            float2 v0 = *(const float2*)&h[s0 * H + lane * 2];
            float2 v1 = *(const float2*)&h[s1 * H + lane * 2];
            acc[0] += e0 * v0.x + e1 * v1.x;
            acc[1] += e0 * v0.y + e1 * v1.y;
        }
        z += e0 + e1;
    }
    if (j < end) {
        int s0 = __ldg(&g_csr[j]);
        float e0 = __expf(leaky(__ldg(&g_as[s0]) + adi));
        if (V == 4) {
            float4 v0 = *(const float4*)&h[s0 * H + lane * 4];
            acc[0] += e0 * v0.x; acc[1] += e0 * v0.y;
            acc[2] += e0 * v0.z; acc[3] += e0 * v0.w;
        } else {
            float2 v0 = *(const float2*)&h[s0 * H + lane * 2];
            acc[0] += e0 * v0.x; acc[1] += e0 * v0.y;
        }
        z += e0;
    }

    float inv = 1.f / z;
#pragma unroll
    for (int v = 0; v < V; v++) {
        float r = acc[v] * inv + bias[lane * V + v];
        out[i * H + lane * V + v] = r > 0.f ? r : 0.f;
    }
}

// ---------------- launch -----------------------------------------------------
extern "C" void kernel_launch(void* const* d_in, const int* in_sizes, int n_in,
                              void* d_out, int out_size) {
    const float* x    = (const float*)d_in[0];
    const int*   ei   = (const int*)d_in[1];       // int32 edge_index [2, E]
    const float* W1   = (const float*)d_in[2];
    const float* a_s1 = (const float*)d_in[3];
    const float* a_d1 = (const float*)d_in[4];
    const float* b1   = (const float*)d_in[5];
    const float* W2   = (const float*)d_in[6];
    const float* a_s2 = (const float*)d_in[7];
    const float* a_d2 = (const float*)d_in[8];
    const float* b2   = (const float*)d_in[9];
    const float* Wp   = (const float*)d_in[10];
    const float* bp   = (const float*)d_in[11];
    const int E = in_sizes[1] / 2;

    const int TB = 256;
    const int edgeBlocks4 = (E + TB * 4 - 1) / (TB * 4);

    // CSR build (zero_deg also zeroes g_as/g_ad for layer-1 fused dots)
    zero_deg_kernel<<<(N_NODES + TB - 1) / TB, TB>>>();
    hist_kernel<<<edgeBlocks4, TB>>>(ei, E);
    scan_kernel<<<1, 1024>>>();
    fill_kernel<<<edgeBlocks4, TB>>>(ei, E);

    const int warpBlocks = (N_NODES * 32 + TB - 1) / TB;

    // layer 1: h1 = x @ W1 (+fused dots) ; x1 = agg(h1)
    dim3 g1(H1 / 64, (N_NODES + 63) / 64);
    gemm_kernel<<<g1, TB>>>(x, -1, W1, nullptr, nullptr, 0, N_NODES, H1, D_IN,
                            a_s1, a_d1);
    gat_agg_kernel<H1><<<warpBlocks, TB>>>(b1);

    // layer 2: h2 = x1 @ W2 (+fused dots) ; x2 = agg(h2)
    zero_attn_kernel<<<(N_NODES + TB - 1) / TB, TB>>>();
    dim3 g2(H2 / 64, (N_NODES + 63) / 64);
    gemm_kernel<<<g2, TB>>>(nullptr, 1, W2, nullptr, nullptr, 2, N_NODES, H2, H1,
                            a_s2, a_d2);
    gat_agg_kernel<H2><<<warpBlocks, TB>>>(b2);

    // projection: out = x2 @ Wp + bp
    dim3 g3(EMB / 64, (N_NODES + 63) / 64);
    gemm_kernel<<<g3, TB>>>(nullptr, 3, Wp, bp, (float*)d_out, -1, N_NODES, EMB, H2,
                            nullptr, nullptr);
}

// round 5
// speedup vs baseline: 1.2078x; 1.1617x over previous
#include <cuda_runtime.h>

#define N_NODES 10000
#define D_IN    128
#define H1      128
#define H2      64
#define EMB     64
#define CAP     256      // fixed bucket capacity per destination node
#define NEG_SLOPE 0.2f

// ---------------- scratch (device globals; no allocation allowed) -----------
__device__ float g_h1[N_NODES * H1];
__device__ float g_x1[N_NODES * H1];
__device__ float g_h2[N_NODES * H2];
__device__ float g_x2[N_NODES * H2];
__device__ float g_as[N_NODES];
__device__ float g_ad[N_NODES];
__device__ int   g_cnt[N_NODES];
__device__ int   g_csr[N_NODES * CAP];   // bucket CSR: row i at i*CAP

// device-side scratch selector (host never touches device symbols)
__device__ __forceinline__ float* buf(int sel) {
    switch (sel) {
        case 0: return g_h1;
        case 1: return g_x1;
        case 2: return g_h2;
        default: return g_x2;
    }
}

// ---------------- init -------------------------------------------------------
__global__ void zero_init_kernel() {
    int i = blockIdx.x * blockDim.x + threadIdx.x;
    if (i < N_NODES) {
        g_cnt[i] = 0;
        g_as[i] = 0.f;
        g_ad[i] = 0.f;
    }
}

__global__ void zero_attn_kernel() {
    int i = blockIdx.x * blockDim.x + threadIdx.x;
    if (i < N_NODES) {
        g_as[i] = 0.f;
        g_ad[i] = 0.f;
    }
}

// ---------------- single-pass bucket CSR fill --------------------------------
// edge_index int32: row 0 = src (E entries), row 1 = dst (E entries).
// 2 edges/thread: 2-deep atomic ILP while keeping the grid large (occupancy).
__global__ void fill_bucket_kernel(const int* __restrict__ ei, int E) {
    int t = blockIdx.x * blockDim.x + threadIdx.x;
    int e0 = t * 2;
    if (e0 >= E) return;
    if (e0 + 2 <= E && ((E & 1) == 0)) {
        int2 s2 = *(const int2*)&ei[e0];
        int2 d2 = *(const int2*)&ei[E + e0];
        int p0 = ((unsigned)d2.x < N_NODES) ? atomicAdd(&g_cnt[d2.x], 1) : CAP;
        int p1 = ((unsigned)d2.y < N_NODES) ? atomicAdd(&g_cnt[d2.y], 1) : CAP;
        if (p0 < CAP && (unsigned)s2.x < N_NODES) g_csr[d2.x * CAP + p0] = s2.x;
        if (p1 < CAP && (unsigned)s2.y < N_NODES) g_csr[d2.y * CAP + p1] = s2.y;
    } else {
        for (int e = e0; e < E && e < e0 + 2; e++) {
            int s = ei[e];
            int d = ei[E + e];
            if ((unsigned)s < N_NODES && (unsigned)d < N_NODES) {
                int pos = atomicAdd(&g_cnt[d], 1);
                if (pos < CAP) g_csr[d * CAP + pos] = s;
            }
        }
    }
}

// ---------------- fp32 tiled GEMM: C[M,Nn] = A[M,K] @ B[K,Nn] (+bias) -------
// If a_src != nullptr, also accumulates per-row attention dots into g_as/g_ad
// (which must be zeroed beforehand).
__global__ void gemm_kernel(const float* __restrict__ Aext, int a_sel,
                            const float* __restrict__ B,
                            const float* __restrict__ bias,
                            float* __restrict__ Cext, int c_sel,
                            int M, int Nn, int K,
                            const float* __restrict__ a_src,
                            const float* __restrict__ a_dst) {
    const float* A = Aext ? Aext : buf(a_sel);
    float*       C = Cext ? Cext : buf(c_sel);

    __shared__ __align__(16) float As[8][64];
    __shared__ __align__(16) float Bs[8][64];
    const int tid  = threadIdx.x;             // 256 threads
    const int trow = tid >> 4;                // 0..15
    const int tcol = tid & 15;                // 0..15
    const int m0 = blockIdx.y * 64;
    const int n0 = blockIdx.x * 64;
    float acc[4][4] = {};

    for (int k0 = 0; k0 < K; k0 += 8) {
        for (int t = tid; t < 512; t += 256) {
            int r = t >> 3, c = t & 7;
            int gr = m0 + r;
            As[c][r] = (gr < M) ? A[gr * K + k0 + c] : 0.f;
        }
        for (int t = tid; t < 512; t += 256) {
            int r = t >> 6, c = t & 63;
            Bs[r][c] = B[(k0 + r) * Nn + n0 + c];
        }
        __syncthreads();
#pragma unroll
        for (int kk = 0; kk < 8; kk++) {
            float4 a4 = *(const float4*)&As[kk][trow * 4];
            float4 b4 = *(const float4*)&Bs[kk][tcol * 4];
            float a[4] = {a4.x, a4.y, a4.z, a4.w};
            float b[4] = {b4.x, b4.y, b4.z, b4.w};
#pragma unroll
            for (int i = 0; i < 4; i++)
#pragma unroll
                for (int j = 0; j < 4; j++)
                    acc[i][j] += a[i] * b[j];
        }
        __syncthreads();
    }

#pragma unroll
    for (int i = 0; i < 4; i++) {
        int row = m0 + trow * 4 + i;
        if (row < M) {
#pragma unroll
            for (int j = 0; j < 4; j++) {
                int col = n0 + tcol * 4 + j;
                float v = acc[i][j];
                if (bias) v += bias[col];
                C[row * Nn + col] = v;
            }
        }
    }

    // fused attention dots: per-row reduction over this block's 64 columns
    if (a_src) {
        float asv[4], adv[4];
#pragma unroll
        for (int j = 0; j < 4; j++) {
            asv[j] = a_src[n0 + tcol * 4 + j];
            adv[j] = a_dst[n0 + tcol * 4 + j];
        }
#pragma unroll
        for (int i = 0; i < 4; i++) {
            float ds = 0.f, dd = 0.f;
#pragma unroll
            for (int j = 0; j < 4; j++) {
                ds += acc[i][j] * asv[j];
                dd += acc[i][j] * adv[j];
            }
#pragma unroll
            for (int off = 8; off; off >>= 1) {
                ds += __shfl_xor_sync(0xffffffffu, ds, off);
                dd += __shfl_xor_sync(0xffffffffu, dd, off);
            }
            int row = m0 + trow * 4 + i;
            if (tcol == 0 && row < M) {
                atomicAdd(&g_as[row], ds);
                atomicAdd(&g_ad[row], dd);
            }
        }
    }
}

__device__ __forceinline__ float leaky(float x) {
    return x > 0.f ? x : NEG_SLOPE * x;
}

// ---------------- GAT aggregation: warp per destination node ----------------
// Single pass softmax (no max subtraction needed), 4-deep gather pipelining.
template <int H>
__global__ void gat_agg_kernel(const float* __restrict__ bias) {
    const float* h;
    float* out;
    if (H == 128) { h = g_h1; out = g_x1; }
    else          { h = g_h2; out = g_x2; }

    int i = (blockIdx.x * blockDim.x + threadIdx.x) >> 5;
    if (i >= N_NODES) return;
    int lane = threadIdx.x & 31;

    float adi = g_ad[i];
    int deg = g_cnt[i];
    if (deg > CAP) deg = CAP;
    const int* row = &g_csr[i * CAP];

    constexpr int V = H / 32;
    // self loop
    float es = __expf(leaky(g_as[i] + adi));
    float z = es;
    float acc[V];
#pragma unroll
    for (int v = 0; v < V; v++) acc[v] = es * h[i * H + lane * V + v];

    int j = 0;
    // unrolled x4: four independent gather chains in flight
    for (; j + 4 <= deg; j += 4) {
        int s0 = __ldg(&row[j]);
        int s1 = __ldg(&row[j + 1]);
        int s2 = __ldg(&row[j + 2]);
        int s3 = __ldg(&row[j + 3]);
        float e0 = __expf(leaky(__ldg(&g_as[s0]) + adi));
        float e1 = __expf(leaky(__ldg(&g_as[s1]) + adi));
        float e2 = __expf(leaky(__ldg(&g_as[s2]) + adi));
        float e3 = __expf(leaky(__ldg(&g_as[s3]) + adi));
        if (V == 4) {
            float4 v0 = *(const float4*)&h[s0 * H + lane * 4];
            float4 v1 = *(const float4*)&h[s1 * H + lane * 4];
            float4 v2 = *(const float4*)&h[s2 * H + lane * 4];
            float4 v3 = *(const float4*)&h[s3 * H + lane * 4];
            acc[0] += e0 * v0.x + e1 * v1.x + e2 * v2.x + e3 * v3.x;
            acc[1] += e0 * v0.y + e1 * v1.y + e2 * v2.y + e3 * v3.y;
            acc[2] += e0 * v0.z + e1 * v1.z + e2 * v2.z + e3 * v3.z;
            acc[3] += e0 * v0.w + e1 * v1.w + e2 * v2.w + e3 * v3.w;
        } else {
            float2 v0 = *(const float2*)&h[s0 * H + lane * 2];
            float2 v1 = *(const float2*)&h[s1 * H + lane * 2];
            float2 v2 = *(const float2*)&h[s2 * H + lane * 2];
            float2 v3 = *(const float2*)&h[s3 * H + lane * 2];
            acc[0] += e0 * v0.x + e1 * v1.x + e2 * v2.x + e3 * v3.x;
            acc[1] += e0 * v0.y + e1 * v1.y + e2 * v2.y + e3 * v3.y;
        }
        z += (e0 + e1) + (e2 + e3);
    }
    for (; j < deg; ++j) {
        int s0 = __ldg(&row[j]);
        float e0 = __expf(leaky(__ldg(&g_as[s0]) + adi));
        if (V == 4) {
            float4 v0 = *(const float4*)&h[s0 * H + lane * 4];
            acc[0] += e0 * v0.x; acc[1] += e0 * v0.y;
            acc[2] += e0 * v0.z; acc[3] += e0 * v0.w;
        } else {
            float2 v0 = *(const float2*)&h[s0 * H + lane * 2];
            acc[0] += e0 * v0.x; acc[1] += e0 * v0.y;
        }
        z += e0;
    }

    float inv = 1.f / z;
#pragma unroll
    for (int v = 0; v < V; v++) {
        float r = acc[v] * inv + bias[lane * V + v];
        out[i * H + lane * V + v] = r > 0.f ? r : 0.f;
    }
}

// ---------------- launch -----------------------------------------------------
extern "C" void kernel_launch(void* const* d_in, const int* in_sizes, int n_in,
                              void* d_out, int out_size) {
    const float* x    = (const float*)d_in[0];
    const int*   ei   = (const int*)d_in[1];       // int32 edge_index [2, E]
    const float* W1   = (const float*)d_in[2];
    const float* a_s1 = (const float*)d_in[3];
    const float* a_d1 = (const float*)d_in[4];
    const float* b1   = (const float*)d_in[5];
    const float* W2   = (const float*)d_in[6];
    const float* a_s2 = (const float*)d_in[7];
    const float* a_d2 = (const float*)d_in[8];
    const float* b2   = (const float*)d_in[9];
    const float* Wp   = (const float*)d_in[10];
    const float* bp   = (const float*)d_in[11];
    const int E = in_sizes[1] / 2;

    const int TB = 256;

    // bucket CSR build: zero counters (+ as/ad for layer1), one atomic pass
    zero_init_kernel<<<(N_NODES + TB - 1) / TB, TB>>>();
    fill_bucket_kernel<<<(E + TB * 2 - 1) / (TB * 2), TB>>>(ei, E);

    const int warpBlocks = (N_NODES * 32 + TB - 1) / TB;

    // layer 1: h1 = x @ W1 (+fused dots) ; x1 = agg(h1)
    dim3 g1(H1 / 64, (N_NODES + 63) / 64);
    gemm_kernel<<<g1, TB>>>(x, -1, W1, nullptr, nullptr, 0, N_NODES, H1, D_IN,
                            a_s1, a_d1);
    gat_agg_kernel<H1><<<warpBlocks, TB>>>(b1);

    // layer 2: h2 = x1 @ W2 (+fused dots) ; x2 = agg(h2)
    zero_attn_kernel<<<(N_NODES + TB - 1) / TB, TB>>>();
    dim3 g2(H2 / 64, (N_NODES + 63) / 64);
    gemm_kernel<<<g2, TB>>>(nullptr, 1, W2, nullptr, nullptr, 2, N_NODES, H2, H1,
                            a_s2, a_d2);
    gat_agg_kernel<H2><<<warpBlocks, TB>>>(b2);

    // projection: out = x2 @ Wp + bp
    dim3 g3(EMB / 64, (N_NODES + 63) / 64);
    gemm_kernel<<<g3, TB>>>(nullptr, 3, Wp, bp, (float*)d_out, -1, N_NODES, EMB, H2,
                            nullptr, nullptr);
}

// round 6
// speedup vs baseline: 1.2796x; 1.0595x over previous
#include <cuda_runtime.h>

#define N_NODES 10000
#define D_IN    128
#define H1      128
#define H2      64
#define EMB     64
#define CAP     256      // fixed bucket capacity per destination node
#define NEG_SLOPE 0.2f
#define FULLMASK 0xffffffffu

// ---------------- scratch (device globals; no allocation allowed) -----------
__device__ float g_h1[N_NODES * H1];
__device__ float g_x1[N_NODES * H1];
__device__ float g_h2[N_NODES * H2];
__device__ float g_x2[N_NODES * H2];
__device__ float g_as[N_NODES];
__device__ float g_ad[N_NODES];
__device__ int   g_cnt[N_NODES];
__device__ int   g_csr[N_NODES * CAP];   // bucket CSR: row i at i*CAP

// device-side scratch selector (host never touches device symbols)
__device__ __forceinline__ float* buf(int sel) {
    switch (sel) {
        case 0: return g_h1;
        case 1: return g_x1;
        case 2: return g_h2;
        default: return g_x2;
    }
}

// ---------------- init -------------------------------------------------------
__global__ void zero_init_kernel() {
    int i = blockIdx.x * blockDim.x + threadIdx.x;
    if (i < N_NODES) {
        g_cnt[i] = 0;
        g_as[i] = 0.f;
        g_ad[i] = 0.f;
    }
}

// ---------------- single-pass bucket CSR fill --------------------------------
// edge_index int32: row 0 = src (E entries), row 1 = dst (E entries).
__global__ void fill_bucket_kernel(const int* __restrict__ ei, int E) {
    int t = blockIdx.x * blockDim.x + threadIdx.x;
    int e0 = t * 2;
    if (e0 >= E) return;
    if (e0 + 2 <= E && ((E & 1) == 0)) {
        int2 s2 = *(const int2*)&ei[e0];
        int2 d2 = *(const int2*)&ei[E + e0];
        int p0 = ((unsigned)d2.x < N_NODES) ? atomicAdd(&g_cnt[d2.x], 1) : CAP;
        int p1 = ((unsigned)d2.y < N_NODES) ? atomicAdd(&g_cnt[d2.y], 1) : CAP;
        if (p0 < CAP && (unsigned)s2.x < N_NODES) g_csr[d2.x * CAP + p0] = s2.x;
        if (p1 < CAP && (unsigned)s2.y < N_NODES) g_csr[d2.y * CAP + p1] = s2.y;
    } else {
        for (int e = e0; e < E && e < e0 + 2; e++) {
            int s = ei[e];
            int d = ei[E + e];
            if ((unsigned)s < N_NODES && (unsigned)d < N_NODES) {
                int pos = atomicAdd(&g_cnt[d], 1);
                if (pos < CAP) g_csr[d * CAP + pos] = s;
            }
        }
    }
}

// ---------------- fp32 tiled GEMM: C[M,Nn] = A[M,K] @ B[K,Nn] (+bias) -------
// If a_src != nullptr, also computes per-row attention dots into g_as/g_ad.
// When gridDim.x == 1 the 64-col block covers all columns -> direct store;
// otherwise atomicAdd (g_as/g_ad must be pre-zeroed).
__global__ void gemm_kernel(const float* __restrict__ Aext, int a_sel,
                            const float* __restrict__ B,
                            const float* __restrict__ bias,
                            float* __restrict__ Cext, int c_sel,
                            int M, int Nn, int K,
                            const float* __restrict__ a_src,
                            const float* __restrict__ a_dst) {
    const float* A = Aext ? Aext : buf(a_sel);
    float*       C = Cext ? Cext : buf(c_sel);

    __shared__ __align__(16) float As[8][64];
    __shared__ __align__(16) float Bs[8][64];
    const int tid  = threadIdx.x;             // 256 threads
    const int trow = tid >> 4;                // 0..15
    const int tcol = tid & 15;                // 0..15
    const int m0 = blockIdx.y * 64;
    const int n0 = blockIdx.x * 64;
    float acc[4][4] = {};

    for (int k0 = 0; k0 < K; k0 += 8) {
        for (int t = tid; t < 512; t += 256) {
            int r = t >> 3, c = t & 7;
            int gr = m0 + r;
            As[c][r] = (gr < M) ? A[gr * K + k0 + c] : 0.f;
        }
        for (int t = tid; t < 512; t += 256) {
            int r = t >> 6, c = t & 63;
            Bs[r][c] = B[(k0 + r) * Nn + n0 + c];
        }
        __syncthreads();
#pragma unroll
        for (int kk = 0; kk < 8; kk++) {
            float4 a4 = *(const float4*)&As[kk][trow * 4];
            float4 b4 = *(const float4*)&Bs[kk][tcol * 4];
            float a[4] = {a4.x, a4.y, a4.z, a4.w};
            float b[4] = {b4.x, b4.y, b4.z, b4.w};
#pragma unroll
            for (int i = 0; i < 4; i++)
#pragma unroll
                for (int j = 0; j < 4; j++)
                    acc[i][j] += a[i] * b[j];
        }
        __syncthreads();
    }

#pragma unroll
    for (int i = 0; i < 4; i++) {
        int row = m0 + trow * 4 + i;
        if (row < M) {
#pragma unroll
            for (int j = 0; j < 4; j++) {
                int col = n0 + tcol * 4 + j;
                float v = acc[i][j];
                if (bias) v += bias[col];
                C[row * Nn + col] = v;
            }
        }
    }

    // fused attention dots: per-row reduction over this block's 64 columns
    if (a_src) {
        float asv[4], adv[4];
#pragma unroll
        for (int j = 0; j < 4; j++) {
            asv[j] = a_src[n0 + tcol * 4 + j];
            adv[j] = a_dst[n0 + tcol * 4 + j];
        }
        bool direct = (gridDim.x == 1);
#pragma unroll
        for (int i = 0; i < 4; i++) {
            float ds = 0.f, dd = 0.f;
#pragma unroll
            for (int j = 0; j < 4; j++) {
                ds += acc[i][j] * asv[j];
                dd += acc[i][j] * adv[j];
            }
#pragma unroll
            for (int off = 8; off; off >>= 1) {
                ds += __shfl_xor_sync(FULLMASK, ds, off);
                dd += __shfl_xor_sync(FULLMASK, dd, off);
            }
            int row = m0 + trow * 4 + i;
            if (tcol == 0 && row < M) {
                if (direct) {
                    g_as[row] = ds;
                    g_ad[row] = dd;
                } else {
                    atomicAdd(&g_as[row], ds);
                    atomicAdd(&g_ad[row], dd);
                }
            }
        }
    }
}

__device__ __forceinline__ float leaky(float x) {
    return x > 0.f ? x : NEG_SLOPE * x;
}

// ---------------- GAT aggregation: warp per destination node ----------------
// Chunked: each lane computes the attention weight for ITS OWN edge (1 gather +
// 1 exp per lane per 32 edges), then weights/indices are shfl-broadcast into a
// feature-gather loop with 4 independent float4 chains in flight.
template <int H>
__global__ void gat_agg_kernel(const float* __restrict__ bias) {
    const float* h;
    float* out;
    if (H == 128) { h = g_h1; out = g_x1; }
    else          { h = g_h2; out = g_x2; }

    int i = (blockIdx.x * blockDim.x + threadIdx.x) >> 5;
    if (i >= N_NODES) return;
    int lane = threadIdx.x & 31;

    float adi = g_ad[i];
    int deg = g_cnt[i];
    if (deg > CAP) deg = CAP;
    const int* row = &g_csr[i * CAP];

    constexpr int V = H / 32;
    // self loop
    float es = __expf(leaky(g_as[i] + adi));
    float zl = (lane == 0) ? es : 0.f;       // per-lane z, reduced once at end
    float acc[V];
#pragma unroll
    for (int v = 0; v < V; v++) acc[v] = es * h[i * H + lane * V + v];

    for (int base = 0; base < deg; base += 32) {
        int rem = deg - base;
        if (rem > 32) rem = 32;

        // each lane: weight for its own edge
        int   idx = 0;
        float e   = 0.f;
        if (lane < rem) {
            idx = __ldg(&row[base + lane]);
            e   = __expf(leaky(__ldg(&g_as[idx]) + adi));
        }
        zl += e;

        int k = 0;
        for (; k + 4 <= rem; k += 4) {
            int   s0 = __shfl_sync(FULLMASK, idx, k);
            int   s1 = __shfl_sync(FULLMASK, idx, k + 1);
            int   s2 = __shfl_sync(FULLMASK, idx, k + 2);
            int   s3 = __shfl_sync(FULLMASK, idx, k + 3);
            float w0 = __shfl_sync(FULLMASK, e, k);
            float w1 = __shfl_sync(FULLMASK, e, k + 1);
            float w2 = __shfl_sync(FULLMASK, e, k + 2);
            float w3 = __shfl_sync(FULLMASK, e, k + 3);
            if (V == 4) {
                float4 v0 = *(const float4*)&h[s0 * H + lane * 4];
                float4 v1 = *(const float4*)&h[s1 * H + lane * 4];
                float4 v2 = *(const float4*)&h[s2 * H + lane * 4];
                float4 v3 = *(const float4*)&h[s3 * H + lane * 4];
                acc[0] += w0 * v0.x + w1 * v1.x + w2 * v2.x + w3 * v3.x;
                acc[1] += w0 * v0.y + w1 * v1.y + w2 * v2.y + w3 * v3.y;
                acc[2] += w0 * v0.z + w1 * v1.z + w2 * v2.z + w3 * v3.z;
                acc[3] += w0 * v0.w + w1 * v1.w + w2 * v2.w + w3 * v3.w;
            } else {
                float2 v0 = *(const float2*)&h[s0 * H + lane * 2];
                float2 v1 = *(const float2*)&h[s1 * H + lane * 2];
                float2 v2 = *(const float2*)&h[s2 * H + lane * 2];
                float2 v3 = *(const float2*)&h[s3 * H + lane * 2];
                acc[0] += w0 * v0.x + w1 * v1.x + w2 * v2.x + w3 * v3.x;
                acc[1] += w0 * v0.y + w1 * v1.y + w2 * v2.y + w3 * v3.y;
            }
        }
        for (; k < rem; ++k) {
            int   s0 = __shfl_sync(FULLMASK, idx, k);
            float w0 = __shfl_sync(FULLMASK, e, k);
            if (V == 4) {
                float4 v0 = *(const float4*)&h[s0 * H + lane * 4];
                acc[0] += w0 * v0.x; acc[1] += w0 * v0.y;
                acc[2] += w0 * v0.z; acc[3] += w0 * v0.w;
            } else {
                float2 v0 = *(const float2*)&h[s0 * H + lane * 2];
                acc[0] += w0 * v0.x; acc[1] += w0 * v0.y;
            }
        }
    }

    // reduce z across lanes
#pragma unroll
    for (int off = 16; off; off >>= 1) zl += __shfl_xor_sync(FULLMASK, zl, off);

    float inv = 1.f / zl;
#pragma unroll
    for (int v = 0; v < V; v++) {
        float r = acc[v] * inv + bias[lane * V + v];
        out[i * H + lane * V + v] = r > 0.f ? r : 0.f;
    }
}

// ---------------- launch -----------------------------------------------------
extern "C" void kernel_launch(void* const* d_in, const int* in_sizes, int n_in,
                              void* d_out, int out_size) {
    const float* x    = (const float*)d_in[0];
    const int*   ei   = (const int*)d_in[1];       // int32 edge_index [2, E]
    const float* W1   = (const float*)d_in[2];
    const float* a_s1 = (const float*)d_in[3];
    const float* a_d1 = (const float*)d_in[4];
    const float* b1   = (const float*)d_in[5];
    const float* W2   = (const float*)d_in[6];
    const float* a_s2 = (const float*)d_in[7];
    const float* a_d2 = (const float*)d_in[8];
    const float* b2   = (const float*)d_in[9];
    const float* Wp   = (const float*)d_in[10];
    const float* bp   = (const float*)d_in[11];
    const int E = in_sizes[1] / 2;

    const int TB = 256;

    // bucket CSR build: zero counters (+ as/ad for layer1), one atomic pass
    zero_init_kernel<<<(N_NODES + TB - 1) / TB, TB>>>();
    fill_bucket_kernel<<<(E + TB * 2 - 1) / (TB * 2), TB>>>(ei, E);

    const int warpBlocks = (N_NODES * 32 + TB - 1) / TB;

    // layer 1: h1 = x @ W1 (+fused dots, atomic: 2 col-blocks) ; x1 = agg(h1)
    dim3 g1(H1 / 64, (N_NODES + 63) / 64);
    gemm_kernel<<<g1, TB>>>(x, -1, W1, nullptr, nullptr, 0, N_NODES, H1, D_IN,
                            a_s1, a_d1);
    gat_agg_kernel<H1><<<warpBlocks, TB>>>(b1);

    // layer 2: h2 = x1 @ W2 (+fused dots, direct store: 1 col-block) ; x2 = agg(h2)
    dim3 g2(H2 / 64, (N_NODES + 63) / 64);
    gemm_kernel<<<g2, TB>>>(nullptr, 1, W2, nullptr, nullptr, 2, N_NODES, H2, H1,
                            a_s2, a_d2);
    gat_agg_kernel<H2><<<warpBlocks, TB>>>(b2);

    // projection: out = x2 @ Wp + bp
    dim3 g3(EMB / 64, (N_NODES + 63) / 64);
    gemm_kernel<<<g3, TB>>>(nullptr, 3, Wp, bp, (float*)d_out, -1, N_NODES, EMB, H2,
                            nullptr, nullptr);
}

// round 7
// speedup vs baseline: 1.3877x; 1.0845x over previous
#include <cuda_runtime.h>
#include <cuda_fp16.h>

#define N_NODES 10000
#define D_IN    128
#define H1      128
#define H2      64
#define EMB     64
#define CAP     256      // fixed bucket capacity per destination node
#define NEG_SLOPE 0.2f
#define FULLMASK 0xffffffffu

// ---------------- scratch (device globals; no allocation allowed) -----------
__device__ __half g_h1h[N_NODES * H1];   // GEMM outputs stored fp16 (gather payload)
__device__ __half g_h2h[N_NODES * H2];
__device__ float  g_x1[N_NODES * H1];    // agg outputs stay fp32 (GEMM A operands)
__device__ float  g_x2[N_NODES * H2];
__device__ float  g_as[N_NODES];
__device__ float  g_ad[N_NODES];
__device__ int    g_cnt[N_NODES];
__device__ int    g_csr[N_NODES * CAP];  // bucket CSR: row i at i*CAP

__device__ __forceinline__ const float* abuf(int sel) {
    return (sel == 1) ? g_x1 : g_x2;
}

// ---------------- init -------------------------------------------------------
__global__ void zero_init_kernel() {
    int i = blockIdx.x * blockDim.x + threadIdx.x;
    if (i < N_NODES) {
        g_cnt[i] = 0;
        g_as[i] = 0.f;
        g_ad[i] = 0.f;
    }
}

// ---------------- single-pass bucket CSR fill --------------------------------
__global__ void fill_bucket_kernel(const int* __restrict__ ei, int E) {
    int t = blockIdx.x * blockDim.x + threadIdx.x;
    int e0 = t * 2;
    if (e0 >= E) return;
    if (e0 + 2 <= E && ((E & 1) == 0)) {
        int2 s2 = *(const int2*)&ei[e0];
        int2 d2 = *(const int2*)&ei[E + e0];
        int p0 = ((unsigned)d2.x < N_NODES) ? atomicAdd(&g_cnt[d2.x], 1) : CAP;
        int p1 = ((unsigned)d2.y < N_NODES) ? atomicAdd(&g_cnt[d2.y], 1) : CAP;
        if (p0 < CAP && (unsigned)s2.x < N_NODES) g_csr[d2.x * CAP + p0] = s2.x;
        if (p1 < CAP && (unsigned)s2.y < N_NODES) g_csr[d2.y * CAP + p1] = s2.y;
    } else {
        for (int e = e0; e < E && e < e0 + 2; e++) {
            int s = ei[e];
            int d = ei[E + e];
            if ((unsigned)s < N_NODES && (unsigned)d < N_NODES) {
                int pos = atomicAdd(&g_cnt[d], 1);
                if (pos < CAP) g_csr[d * CAP + pos] = s;
            }
        }
    }
}

// ---------------- fp32 tiled GEMM ---------------------------------------------
// C = A @ B (+bias). Output either fp32 (Cext) or fp16 scratch (h_sel: 0->g_h1h,
// 1->g_h2h). If a_src != nullptr, also computes per-row attention dots into
// g_as/g_ad (direct store when gridDim.x==1, else atomicAdd into pre-zeroed).
__global__ void gemm_kernel(const float* __restrict__ Aext, int a_sel,
                            const float* __restrict__ B,
                            const float* __restrict__ bias,
                            float* __restrict__ Cext, int h_sel,
                            int M, int Nn, int K,
                            const float* __restrict__ a_src,
                            const float* __restrict__ a_dst) {
    const float* A = Aext ? Aext : abuf(a_sel);

    __shared__ __align__(16) float As[8][64];
    __shared__ __align__(16) float Bs[8][64];
    const int tid  = threadIdx.x;             // 256 threads
    const int trow = tid >> 4;                // 0..15
    const int tcol = tid & 15;                // 0..15
    const int m0 = blockIdx.y * 64;
    const int n0 = blockIdx.x * 64;
    float acc[4][4] = {};

    for (int k0 = 0; k0 < K; k0 += 8) {
        for (int t = tid; t < 512; t += 256) {
            int r = t >> 3, c = t & 7;
            int gr = m0 + r;
            As[c][r] = (gr < M) ? A[gr * K + k0 + c] : 0.f;
        }
        for (int t = tid; t < 512; t += 256) {
            int r = t >> 6, c = t & 63;
            Bs[r][c] = B[(k0 + r) * Nn + n0 + c];
        }
        __syncthreads();
#pragma unroll
        for (int kk = 0; kk < 8; kk++) {
            float4 a4 = *(const float4*)&As[kk][trow * 4];
            float4 b4 = *(const float4*)&Bs[kk][tcol * 4];
            float a[4] = {a4.x, a4.y, a4.z, a4.w};
            float b[4] = {b4.x, b4.y, b4.z, b4.w};
#pragma unroll
            for (int i = 0; i < 4; i++)
#pragma unroll
                for (int j = 0; j < 4; j++)
                    acc[i][j] += a[i] * b[j];
        }
        __syncthreads();
    }

    if (Cext) {
#pragma unroll
        for (int i = 0; i < 4; i++) {
            int row = m0 + trow * 4 + i;
            if (row < M) {
#pragma unroll
                for (int j = 0; j < 4; j++) {
                    int col = n0 + tcol * 4 + j;
                    float v = acc[i][j];
                    if (bias) v += bias[col];
                    Cext[row * Nn + col] = v;
                }
            }
        }
    } else {
        __half* Ch = (h_sel == 0) ? g_h1h : g_h2h;
#pragma unroll
        for (int i = 0; i < 4; i++) {
            int row = m0 + trow * 4 + i;
            if (row < M) {
                int col = n0 + tcol * 4;
                __half2 p0 = __floats2half2_rn(acc[i][0], acc[i][1]);
                __half2 p1 = __floats2half2_rn(acc[i][2], acc[i][3]);
                uint2 u;
                u.x = *reinterpret_cast<unsigned*>(&p0);
                u.y = *reinterpret_cast<unsigned*>(&p1);
                *(uint2*)&Ch[row * Nn + col] = u;
            }
        }
    }

    // fused attention dots (from fp32 accumulators)
    if (a_src) {
        float asv[4], adv[4];
#pragma unroll
        for (int j = 0; j < 4; j++) {
            asv[j] = a_src[n0 + tcol * 4 + j];
            adv[j] = a_dst[n0 + tcol * 4 + j];
        }
        bool direct = (gridDim.x == 1);
#pragma unroll
        for (int i = 0; i < 4; i++) {
            float ds = 0.f, dd = 0.f;
#pragma unroll
            for (int j = 0; j < 4; j++) {
                ds += acc[i][j] * asv[j];
                dd += acc[i][j] * adv[j];
            }
#pragma unroll
            for (int off = 8; off; off >>= 1) {
                ds += __shfl_xor_sync(FULLMASK, ds, off);
                dd += __shfl_xor_sync(FULLMASK, dd, off);
            }
            int row = m0 + trow * 4 + i;
            if (tcol == 0 && row < M) {
                if (direct) {
                    g_as[row] = ds;
                    g_ad[row] = dd;
                } else {
                    atomicAdd(&g_as[row], ds);
                    atomicAdd(&g_ad[row], dd);
                }
            }
        }
    }
}

__device__ __forceinline__ float leaky(float x) {
    return x > 0.f ? x : NEG_SLOPE * x;
}

// ---------------- GAT aggregation: warp per destination node ----------------
// Lane-parallel attention weights (1 gather + 1 exp per lane per 32 edges),
// shfl-broadcast into a fp16 feature-gather loop (4 chains in flight).
template <int H>
__global__ void __launch_bounds__(128) gat_agg_kernel(const float* __restrict__ bias) {
    const __half* hb = (H == 128) ? g_h1h : g_h2h;
    float* out       = (H == 128) ? g_x1 : g_x2;

    int i = (blockIdx.x * blockDim.x + threadIdx.x) >> 5;
    if (i >= N_NODES) return;
    int lane = threadIdx.x & 31;

    float adi = g_ad[i];
    int deg = g_cnt[i];
    if (deg > CAP) deg = CAP;
    const int* row = &g_csr[i * CAP];

    constexpr int V = H / 32;
    // self loop
    float es = __expf(leaky(g_as[i] + adi));
    float zl = (lane == 0) ? es : 0.f;
    float acc[V];
    if (V == 4) {
        uint2 u = *(const uint2*)&hb[i * H + lane * 4];
        float2 f0 = __half22float2(*reinterpret_cast<const __half2*>(&u.x));
        float2 f1 = __half22float2(*reinterpret_cast<const __half2*>(&u.y));
        acc[0] = es * f0.x; acc[1] = es * f0.y;
        acc[2] = es * f1.x; acc[3] = es * f1.y;
    } else {
        float2 f = __half22float2(*(const __half2*)&hb[i * H + lane * 2]);
        acc[0] = es * f.x; acc[1] = es * f.y;
    }

    for (int base = 0; base < deg; base += 32) {
        int rem = deg - base;
        if (rem > 32) rem = 32;

        int   idx = 0;
        float e   = 0.f;
        if (lane < rem) {
            idx = __ldg(&row[base + lane]);
            e   = __expf(leaky(__ldg(&g_as[idx]) + adi));
        }
        zl += e;

        int k = 0;
        for (; k + 4 <= rem; k += 4) {
            int   s0 = __shfl_sync(FULLMASK, idx, k);
            int   s1 = __shfl_sync(FULLMASK, idx, k + 1);
            int   s2 = __shfl_sync(FULLMASK, idx, k + 2);
            int   s3 = __shfl_sync(FULLMASK, idx, k + 3);
            float w0 = __shfl_sync(FULLMASK, e, k);
            float w1 = __shfl_sync(FULLMASK, e, k + 1);
            float w2 = __shfl_sync(FULLMASK, e, k + 2);
            float w3 = __shfl_sync(FULLMASK, e, k + 3);
            if (V == 4) {
                uint2 u0 = *(const uint2*)&hb[s0 * H + lane * 4];
                uint2 u1 = *(const uint2*)&hb[s1 * H + lane * 4];
                uint2 u2 = *(const uint2*)&hb[s2 * H + lane * 4];
                uint2 u3 = *(const uint2*)&hb[s3 * H + lane * 4];
                float2 a0 = __half22float2(*reinterpret_cast<const __half2*>(&u0.x));
                float2 b0 = __half22float2(*reinterpret_cast<const __half2*>(&u0.y));
                float2 a1 = __half22float2(*reinterpret_cast<const __half2*>(&u1.x));
                float2 b1 = __half22float2(*reinterpret_cast<const __half2*>(&u1.y));
                float2 a2 = __half22float2(*reinterpret_cast<const __half2*>(&u2.x));
                float2 b2 = __half22float2(*reinterpret_cast<const __half2*>(&u2.y));
                float2 a3 = __half22float2(*reinterpret_cast<const __half2*>(&u3.x));
                float2 b3 = __half22float2(*reinterpret_cast<const __half2*>(&u3.y));
                acc[0] += w0 * a0.x + w1 * a1.x + w2 * a2.x + w3 * a3.x;
                acc[1] += w0 * a0.y + w1 * a1.y + w2 * a2.y + w3 * a3.y;
                acc[2] += w0 * b0.x + w1 * b1.x + w2 * b2.x + w3 * b3.x;
                acc[3] += w0 * b0.y + w1 * b1.y + w2 * b2.y + w3 * b3.y;
            } else {
                float2 f0 = __half22float2(*(const __half2*)&hb[s0 * H + lane * 2]);
                float2 f1 = __half22float2(*(const __half2*)&hb[s1 * H + lane * 2]);
                float2 f2 = __half22float2(*(const __half2*)&hb[s2 * H + lane * 2]);
                float2 f3 = __half22float2(*(const __half2*)&hb[s3 * H + lane * 2]);
                acc[0] += w0 * f0.x + w1 * f1.x + w2 * f2.x + w3 * f3.x;
                acc[1] += w0 * f0.y + w1 * f1.y + w2 * f2.y + w3 * f3.y;
            }
        }
        for (; k < rem; ++k) {
            int   s0 = __shfl_sync(FULLMASK, idx, k);
            float w0 = __shfl_sync(FULLMASK, e, k);
            if (V == 4) {
                uint2 u0 = *(const uint2*)&hb[s0 * H + lane * 4];
                float2 a0 = __half22float2(*reinterpret_cast<const __half2*>(&u0.x));
                float2 b0 = __half22float2(*reinterpret_cast<const __half2*>(&u0.y));
                acc[0] += w0 * a0.x; acc[1] += w0 * a0.y;
                acc[2] += w0 * b0.x; acc[3] += w0 * b0.y;
            } else {
                float2 f0 = __half22float2(*(const __half2*)&hb[s0 * H + lane * 2]);
                acc[0] += w0 * f0.x; acc[1] += w0 * f0.y;
            }
        }
    }

#pragma unroll
    for (int off = 16; off; off >>= 1) zl += __shfl_xor_sync(FULLMASK, zl, off);

    float inv = 1.f / zl;
#pragma unroll
    for (int v = 0; v < V; v++) {
        float r = acc[v] * inv + bias[lane * V + v];
        out[i * H + lane * V + v] = r > 0.f ? r : 0.f;
    }
}

// ---------------- launch -----------------------------------------------------
extern "C" void kernel_launch(void* const* d_in, const int* in_sizes, int n_in,
                              void* d_out, int out_size) {
    const float* x    = (const float*)d_in[0];
    const int*   ei   = (const int*)d_in[1];       // int32 edge_index [2, E]
    const float* W1   = (const float*)d_in[2];
    const float* a_s1 = (const float*)d_in[3];
    const float* a_d1 = (const float*)d_in[4];
    const float* b1   = (const float*)d_in[5];
    const float* W2   = (const float*)d_in[6];
    const float* a_s2 = (const float*)d_in[7];
    const float* a_d2 = (const float*)d_in[8];
    const float* b2   = (const float*)d_in[9];
    const float* Wp   = (const float*)d_in[10];
    const float* bp   = (const float*)d_in[11];
    const int E = in_sizes[1] / 2;

    const int TB = 256;
    const int AB = 128;   // agg block size: finer scheduling granularity

    zero_init_kernel<<<(N_NODES + TB - 1) / TB, TB>>>();
    fill_bucket_kernel<<<(E + TB * 2 - 1) / (TB * 2), TB>>>(ei, E);

    const int aggBlocks = (N_NODES * 32 + AB - 1) / AB;

    // layer 1: h1(fp16) = x @ W1 (+fused dots) ; x1 = agg(h1)
    dim3 g1(H1 / 64, (N_NODES + 63) / 64);
    gemm_kernel<<<g1, TB>>>(x, -1, W1, nullptr, nullptr, 0, N_NODES, H1, D_IN,
                            a_s1, a_d1);
    gat_agg_kernel<H1><<<aggBlocks, AB>>>(b1);

    // layer 2: h2(fp16) = x1 @ W2 (+fused dots, direct store) ; x2 = agg(h2)
    dim3 g2(H2 / 64, (N_NODES + 63) / 64);
    gemm_kernel<<<g2, TB>>>(nullptr, 1, W2, nullptr, nullptr, 1, N_NODES, H2, H1,
                            a_s2, a_d2);
    gat_agg_kernel<H2><<<aggBlocks, AB>>>(b2);

    // projection: out = x2 @ Wp + bp (fp32)
    dim3 g3(EMB / 64, (N_NODES + 63) / 64);
    gemm_kernel<<<g3, TB>>>(nullptr, 2, Wp, bp, (float*)d_out, -1, N_NODES, EMB, H2,
                            nullptr, nullptr);
}